// round 13
// baseline (speedup 1.0000x reference)
#include <cuda_runtime.h>
#include <cuda_fp16.h>
#include <cstdint>

#define KK9 9
#define NJ  18
#define Bn  8
#define Cn  128
#define Hn  64
#define Wn  64
#define On  128
#define HW  (Hn * Wn)
#define BROWB 144                // bytes per B row (64 p * 2B + 16 pad)
#define BROWS 72                 // ushorts per B row
#define SMB_BYTES (128 * BROWB)          // 18432 per buffer (single s plane)
#define SMB_HALF_SHORTS (SMB_BYTES / 2)
// smem layout (mainloop):  B double buffer [0, 36864), s_off fp32 [36864, 41472)
// smem layout (prologue):  partials u64   [0, 18432), wch u64    [18432, 64512)
#define SM_OFF  36864
#define SM_WCH  18432
#define SM_TOT  64512

// ---------------- scratch (no allocations allowed) ---------------------------
// A fragments (single fp16 plane): [kk][ks8(8)][mtile(8)][lane(32)] -> uint4
__device__ uint4 g_wAfrag[KK9 * 8 * 8 * 32];

// ---------------- helpers -----------------------------------------------------
typedef unsigned long long u64t;
__device__ __forceinline__ u64t pack2(float a, float b) {
    u64t r; asm("mov.b64 %0, {%1, %2};" : "=l"(r) : "f"(a), "f"(b)); return r;
}
__device__ __forceinline__ u64t ffma2(u64t a, u64t b, u64t c) {
    u64t d; asm("fma.rn.f32x2 %0, %1, %2, %3;" : "=l"(d) : "l"(a), "l"(b), "l"(c)); return d;
}
__device__ __forceinline__ u64t addf2(u64t a, u64t b) {
    u64t d; asm("add.rn.f32x2 %0, %1, %2;" : "=l"(d) : "l"(a), "l"(b)); return d;
}
__device__ __forceinline__ void unpack2(u64t v, float& lo, float& hi) {
    asm("mov.b64 {%0, %1}, %2;" : "=f"(lo), "=f"(hi) : "l"(v));
}
__device__ __forceinline__ uint32_t smem_u32(const void* p) {
    uint32_t a;
    asm("{ .reg .u64 t; cvta.to.shared.u64 t, %1; cvt.u32.u64 %0, t; }" : "=r"(a) : "l"(p));
    return a;
}
__device__ __forceinline__ uint32_t apack1(const float* w_def, int kk, int m, int c) {
    uint32_t lo = __half_as_ushort(__float2half_rn(w_def[(m * Cn + c) * KK9 + kk]));
    uint32_t hi = __half_as_ushort(__float2half_rn(w_def[(m * Cn + c + 1) * KK9 + kk]));
    return lo | (hi << 16);
}

#define MMA_F16(d, a, b0r, b1r)                                                      \
    asm volatile("mma.sync.aligned.m16n8k16.row.col.f32.f16.f16.f32 "                \
                 "{%0,%1,%2,%3}, {%4,%5,%6,%7}, {%8,%9}, {%0,%1,%2,%3};"             \
                 : "+f"((d)[0]), "+f"((d)[1]), "+f"((d)[2]), "+f"((d)[3])            \
                 : "r"((a).x), "r"((a).y), "r"((a).z), "r"((a).w), "r"(b0r), "r"(b1r))

#define LDSM_X4_TRANS(r0, r1, r2, r3, addr)                                          \
    asm volatile("ldmatrix.sync.aligned.m8n8.x4.trans.shared.b16 {%0,%1,%2,%3}, [%4];" \
                 : "=r"(r0), "=r"(r1), "=r"(r2), "=r"(r3) : "r"(addr))

// sampling metadata from smem offsets
struct Meta {
    float w00, w01, w10, w11;
    int   o00, o01, o10, o11;
    bool  v00, v01, v10, v11;
};
__device__ __forceinline__ Meta make_meta_sm(const float* s_off, int h, int p, int kk) {
    int ky = kk / 3, kx = kk % 3;
    float offy = s_off[(2 * kk) * 64 + p];
    float offx = s_off[(2 * kk + 1) * 64 + p];
    float py = (float)(h - 1 + ky) + offy;
    float px = (float)(p - 1 + kx) + offx;
    float fy = floorf(py), fx = floorf(px);
    int iy0 = (int)fy, ix0 = (int)fx;
    float wy = py - fy, wx = px - fx;
    Meta m;
    m.w00 = (1.f - wy) * (1.f - wx);
    m.w01 = (1.f - wy) * wx;
    m.w10 = wy * (1.f - wx);
    m.w11 = wy * wx;
    int iy1 = iy0 + 1, ix1 = ix0 + 1;
    bool vy0 = (iy0 >= 0) & (iy0 < Hn), vy1 = (iy1 >= 0) & (iy1 < Hn);
    bool vx0 = (ix0 >= 0) & (ix0 < Wn), vx1 = (ix1 >= 0) & (ix1 < Wn);
    m.v00 = vy0 & vx0; m.v01 = vy0 & vx1; m.v10 = vy1 & vx0; m.v11 = vy1 & vx1;
    m.o00 = iy0 * Wn + ix0; m.o01 = iy0 * Wn + ix1;
    m.o10 = iy1 * Wn + ix0; m.o11 = iy1 * Wn + ix1;
    return m;
}
__device__ __forceinline__ void bstore(unsigned short* dst, int c, int p, float s) {
    dst[c * BROWS + p] = __half_as_ushort(__float2half_rn(s));
}

// ---------------------------------------------------------------------------
// Kernel 0: A-fragment prep (tiny)
// ---------------------------------------------------------------------------
__global__ __launch_bounds__(256) void prep_kernel(const float* __restrict__ w_def) {
    int it = blockIdx.x * 256 + threadIdx.x;     // 72 blocks x 256 = 18432
    if (it >= KK9 * 8 * 8 * 32) return;
    int lane = it & 31;
    int mt   = (it >> 5) & 7;
    int ks8  = (it >> 8) & 7;
    int kk   = it >> 11;
    int g  = lane >> 2, tg = lane & 3;
    int cb = ks8 * 16 + 2 * tg;
    int m  = mt * 16 + g;
    uint4 v;
    v.x = apack1(w_def, kk, m,     cb);
    v.y = apack1(w_def, kk, m + 8, cb);
    v.z = apack1(w_def, kk, m,     cb + 8);
    v.w = apack1(w_def, kk, m + 8, cb + 8);
    g_wAfrag[it] = v;
}

// ---------------------------------------------------------------------------
// Kernel 1: fused offsets prologue + pipelined gather + fp16 mma.sync GEMM.
// Block = 256 thr, one output row (b, h): 128 o x 64 p.
// ---------------------------------------------------------------------------
__global__ __launch_bounds__(256, 2) void main_kernel(const float* __restrict__ x,
                                                      const float* __restrict__ w_off,
                                                      const float* __restrict__ b_off,
                                                      const float* __restrict__ b_def,
                                                      float* __restrict__ out) {
    extern __shared__ char sm[];
    unsigned short* sB = (unsigned short*)sm;
    uint32_t smB = smem_u32(sm);
    float* s_off = (float*)(sm + SM_OFF);

    int tid  = threadIdx.x;
    int wid  = tid >> 5;
    int lane = tid & 31;
    int b = blockIdx.x >> 6;
    int h = blockIdx.x & 63;

    int p    = tid & 63;                 // pixel (used in prologue + gather)
    int cq   = tid >> 6;                 // channel quarter

    // ============== PROLOGUE: offset conv for this row ==============
    {
        u64t* wch  = (u64t*)(sm + SM_WCH);      // [cl(64)][jp(9)][10]
        u64t* part = (u64t*)sm;                 // [cq(4)][jp(9)][p(64)]

        u64t acc2[KK9];
#pragma unroll
        for (int jp = 0; jp < KK9; jp++)
            acc2[jp] = (cq == 0) ? pack2(b_off[2 * jp], b_off[2 * jp + 1]) : 0ULL;

        for (int r = 0; r < 2; r++) {
            // stage 64 channels of w_off as (y,x) j-pairs
            __syncthreads();
            for (int i = tid; i < 64 * KK9 * 9; i += 256) {
                int q  = i % 9;
                int jp = (i / 9) % KK9;
                int cl = i / (9 * KK9);
                int c  = r * 64 + cl;
                float lo = w_off[((2 * jp)     * Cn + c) * 9 + q];
                float hi = w_off[((2 * jp + 1) * Cn + c) * 9 + q];
                wch[(cl * KK9 + jp) * 10 + q] = pack2(lo, hi);
            }
            __syncthreads();

            for (int k = 0; k < 16; k++) {
                int cl = cq * 16 + k;
                const float* xb = x + ((size_t)(b * Cn + r * 64 + cl) * Hn) * Wn;
                u64t x2[9];
#pragma unroll
                for (int ky = 0; ky < 3; ky++)
#pragma unroll
                    for (int kx = 0; kx < 3; kx++) {
                        int y = h - 1 + ky, xx = p - 1 + kx;
                        bool v = (y >= 0) & (y < Hn) & (xx >= 0) & (xx < Wn);
                        float xv = v ? xb[y * Wn + xx] : 0.0f;
                        x2[ky * 3 + kx] = pack2(xv, xv);
                    }
#pragma unroll
                for (int jp = 0; jp < KK9; jp++) {
                    const u64t* wp = &wch[(cl * KK9 + jp) * 10];
                    ulonglong2 w01 = *(const ulonglong2*)(wp);
                    ulonglong2 w23 = *(const ulonglong2*)(wp + 2);
                    ulonglong2 w45 = *(const ulonglong2*)(wp + 4);
                    ulonglong2 w67 = *(const ulonglong2*)(wp + 6);
                    u64t       w8  = wp[8];
                    u64t a = acc2[jp];
                    a = ffma2(w01.x, x2[0], a);
                    a = ffma2(w01.y, x2[1], a);
                    a = ffma2(w23.x, x2[2], a);
                    a = ffma2(w23.y, x2[3], a);
                    a = ffma2(w45.x, x2[4], a);
                    a = ffma2(w45.y, x2[5], a);
                    a = ffma2(w67.x, x2[6], a);
                    a = ffma2(w67.y, x2[7], a);
                    a = ffma2(w8,    x2[8], a);
                    acc2[jp] = a;
                }
            }
        }

        // write partials (region [0,18432) — wch untouched)
        __syncthreads();                          // wch reads done block-wide
#pragma unroll
        for (int jp = 0; jp < KK9; jp++)
            part[(cq * KK9 + jp) * 64 + p] = acc2[jp];
        __syncthreads();

        // reduce 4 partials -> s_off[j][p] fp32
        for (int i = tid; i < KK9 * 64; i += 256) {
            u64t s = addf2(addf2(part[i], part[KK9 * 64 + i]),
                           addf2(part[2 * KK9 * 64 + i], part[3 * KK9 * 64 + i]));
            float oy, ox;
            unpack2(s, oy, ox);
            int jp = i / 64, pp = i % 64;
            s_off[(2 * jp) * 64 + pp]     = oy;
            s_off[(2 * jp + 1) * 64 + pp] = ox;
        }
        __syncthreads();
    }

    // ============== GEMM SETUP ==============
    int wm = wid >> 1;
    int wn = wid & 1;
    int g  = lane >> 2, tg = lane & 3;

    float acc[2][4][4];
#pragma unroll
    for (int f = 0; f < 2; f++)
#pragma unroll
        for (int nf = 0; nf < 4; nf++)
#pragma unroll
            for (int q = 0; q < 4; q++) acc[f][nf][q] = 0.0f;

    int cgrp = cq >> 1;                  // 0/1: 64-channel half? no — keep 32c groups
    cgrp = cq;                           // thread = (pixel p, 32-channel group cq)
    const float* xb0 = x + (size_t)(b * Cn + cgrp * 32) * HW;

    int lr    = lane & 7;
    int khalf = ((lane >> 3) & 1) * 8;
    int pgrp  = lane >> 4;
    uint32_t browbase = (uint32_t)((khalf + lr) * BROWB + (wn * 32 + pgrp * 8) * 2);

    // ---- gather kk=0 into buffer 0 ----
    {
        Meta m0 = make_meta_sm(s_off, h, p, 0);
#pragma unroll 8
        for (int ci = 0; ci < 32; ci++) {
            const float* xc = xb0 + ci * HW;
            float a00 = m0.v00 ? xc[m0.o00] : 0.0f;
            float a01 = m0.v01 ? xc[m0.o01] : 0.0f;
            float a10 = m0.v10 ? xc[m0.o10] : 0.0f;
            float a11 = m0.v11 ? xc[m0.o11] : 0.0f;
            float s = a00 * m0.w00 + a01 * m0.w01 + a10 * m0.w10 + a11 * m0.w11;
            bstore(sB, cgrp * 32 + ci, p, s);
        }
    }
    __syncthreads();

    // ---- main pipelined loop over kk ----
    for (int kk = 0; kk < KK9; kk++) {
        uint32_t curOff = (uint32_t)((kk & 1) * SMB_BYTES);
        unsigned short* nxtB = sB + ((kk + 1) & 1) * SMB_HALF_SHORTS;
        bool doG = (kk < KK9 - 1);
        Meta mn;
        if (doG) mn = make_meta_sm(s_off, h, p, kk + 1);
        const uint4* ap = g_wAfrag + (size_t)kk * (8 * 8 * 32);

        for (int ks8 = 0; ks8 < 8; ks8++) {
            float gv[4][4];
            if (doG) {
#pragma unroll
                for (int q = 0; q < 4; q++) {
                    const float* xc = xb0 + (ks8 * 4 + q) * HW;
                    gv[q][0] = mn.v00 ? xc[mn.o00] : 0.0f;
                    gv[q][1] = mn.v01 ? xc[mn.o01] : 0.0f;
                    gv[q][2] = mn.v10 ? xc[mn.o10] : 0.0f;
                    gv[q][3] = mn.v11 ? xc[mn.o11] : 0.0f;
                }
            }

            const uint4* a_hi = ap + ((size_t)ks8 * 8 + wm * 2) * 32 + lane;
            uint4 Ah0 = a_hi[0], Ah1 = a_hi[32];

            uint32_t addr = smB + curOff + browbase + (uint32_t)(ks8 * 16 * BROWB);
            uint32_t b0, b1, b2, b3, b4, b5, b6, b7;
            LDSM_X4_TRANS(b0, b1, b2, b3, addr);
            LDSM_X4_TRANS(b4, b5, b6, b7, addr + 32);

            MMA_F16(acc[0][0], Ah0, b0, b1);
            MMA_F16(acc[0][1], Ah0, b2, b3);
            MMA_F16(acc[0][2], Ah0, b4, b5);
            MMA_F16(acc[0][3], Ah0, b6, b7);
            MMA_F16(acc[1][0], Ah1, b0, b1);
            MMA_F16(acc[1][1], Ah1, b2, b3);
            MMA_F16(acc[1][2], Ah1, b4, b5);
            MMA_F16(acc[1][3], Ah1, b6, b7);

            if (doG) {
#pragma unroll
                for (int q = 0; q < 4; q++) {
                    float s = gv[q][0] * mn.w00 + gv[q][1] * mn.w01
                            + gv[q][2] * mn.w10 + gv[q][3] * mn.w11;
                    bstore(nxtB, cgrp * 32 + ks8 * 4 + q, p, s);
                }
            }
        }
        __syncthreads();
    }

    // ---- Epilogue: D fragment -> gmem with bias ----
#pragma unroll
    for (int f = 0; f < 2; f++) {
        int oo = wm * 32 + f * 16 + g;
        float bd0 = b_def[oo];
        float bd1 = b_def[oo + 8];
        float* orow0 = out + (((size_t)b * On + oo) * Hn + h) * Wn;
        float* orow1 = orow0 + (size_t)8 * HW;
#pragma unroll
        for (int nf = 0; nf < 4; nf++) {
            int pp = wn * 32 + nf * 8 + 2 * tg;
            float2 v0 = { acc[f][nf][0] + bd0, acc[f][nf][1] + bd0 };
            float2 v1 = { acc[f][nf][2] + bd1, acc[f][nf][3] + bd1 };
            *(float2*)(orow0 + pp) = v0;
            *(float2*)(orow1 + pp) = v1;
        }
    }
}

// ---------------------------------------------------------------------------
extern "C" void kernel_launch(void* const* d_in, const int* in_sizes, int n_in,
                              void* d_out, int out_size) {
    const float* x     = (const float*)d_in[0];
    const float* w_off = (const float*)d_in[1];
    const float* b_off = (const float*)d_in[2];
    const float* w_def = (const float*)d_in[3];
    const float* b_def = (const float*)d_in[4];
    float* out = (float*)d_out;

    cudaFuncSetAttribute(main_kernel, cudaFuncAttributeMaxDynamicSharedMemorySize, SM_TOT);

    prep_kernel<<<72, 256>>>(w_def);
    main_kernel<<<Bn * Hn, 256, SM_TOT>>>(x, w_off, b_off, b_def, out);
}

// round 14
// speedup vs baseline: 1.0771x; 1.0771x over previous
#include <cuda_runtime.h>
#include <cuda_fp16.h>
#include <cstdint>

#define KK9 9
#define NJ  18
#define Bn  8
#define Cn  128
#define Hn  64
#define Wn  64
#define On  128
#define HW  (Hn * Wn)
#define NCHUNK 4
#define BROWB 144                // bytes per B row (64 p * 2B + 16 pad)
#define BROWS 72                 // ushorts per B row
#define SMB_BYTES (128 * BROWB)          // 18432 per buffer (single s plane)
#define SMB_HALF_SHORTS (SMB_BYTES / 2)
#define SM_TOT (2 * SMB_BYTES)           // 36864 B double-buffered

// ---------------- scratch (no allocations allowed) ---------------------------
__device__ float g_off_part[NCHUNK * Bn * NJ * Hn * Wn];
// A fragments (single fp16 plane): [kk][ks8(8)][mtile(8)][lane(32)] -> uint4
__device__ uint4 g_wAfrag[KK9 * 8 * 8 * 32];

// ---------------- helpers -----------------------------------------------------
typedef unsigned long long u64t;
__device__ __forceinline__ u64t pack2(float a, float b) {
    u64t r; asm("mov.b64 %0, {%1, %2};" : "=l"(r) : "f"(a), "f"(b)); return r;
}
__device__ __forceinline__ u64t ffma2(u64t a, u64t b, u64t c) {
    u64t d; asm("fma.rn.f32x2 %0, %1, %2, %3;" : "=l"(d) : "l"(a), "l"(b), "l"(c)); return d;
}
__device__ __forceinline__ void unpack2(u64t v, float& lo, float& hi) {
    asm("mov.b64 {%0, %1}, %2;" : "=f"(lo), "=f"(hi) : "l"(v));
}
__device__ __forceinline__ uint32_t smem_u32(const void* p) {
    uint32_t a;
    asm("{ .reg .u64 t; cvta.to.shared.u64 t, %1; cvt.u32.u64 %0, t; }" : "=r"(a) : "l"(p));
    return a;
}
__device__ __forceinline__ uint32_t apack1(const float* w_def, int kk, int m, int c) {
    uint32_t lo = __half_as_ushort(__float2half_rn(w_def[(m * Cn + c) * KK9 + kk]));
    uint32_t hi = __half_as_ushort(__float2half_rn(w_def[(m * Cn + c + 1) * KK9 + kk]));
    return lo | (hi << 16);
}

#define MMA_F16(d, a, b0r, b1r)                                                      \
    asm volatile("mma.sync.aligned.m16n8k16.row.col.f32.f16.f16.f32 "                \
                 "{%0,%1,%2,%3}, {%4,%5,%6,%7}, {%8,%9}, {%0,%1,%2,%3};"             \
                 : "+f"((d)[0]), "+f"((d)[1]), "+f"((d)[2]), "+f"((d)[3])            \
                 : "r"((a).x), "r"((a).y), "r"((a).z), "r"((a).w), "r"(b0r), "r"(b1r))

#define LDSM_X4_TRANS(r0, r1, r2, r3, addr)                                          \
    asm volatile("ldmatrix.sync.aligned.m8n8.x4.trans.shared.b16 {%0,%1,%2,%3}, [%4];" \
                 : "=r"(r0), "=r"(r1), "=r"(r2), "=r"(r3) : "r"(addr))

// sampling metadata recomputed per (p, kk)
struct Meta {
    float w00, w01, w10, w11;
    int   o00, o01, o10, o11;
    bool  v00, v01, v10, v11;
};
__device__ __forceinline__ Meta make_meta(int b, int h, int p, int kk) {
    const size_t CS = (size_t)Bn * NJ * Hn * Wn;
    int ky = kk / 3, kx = kk % 3;
    size_t by = ((size_t)(b * NJ + 2 * kk) * Hn + h) * Wn + p;
    size_t bx = by + (size_t)HW;
    float offy = g_off_part[by] + g_off_part[CS + by]
               + g_off_part[2 * CS + by] + g_off_part[3 * CS + by];
    float offx = g_off_part[bx] + g_off_part[CS + bx]
               + g_off_part[2 * CS + bx] + g_off_part[3 * CS + bx];
    float py = (float)(h - 1 + ky) + offy;
    float px = (float)(p - 1 + kx) + offx;
    float fy = floorf(py), fx = floorf(px);
    int iy0 = (int)fy, ix0 = (int)fx;
    float wy = py - fy, wx = px - fx;
    Meta m;
    m.w00 = (1.f - wy) * (1.f - wx);
    m.w01 = (1.f - wy) * wx;
    m.w10 = wy * (1.f - wx);
    m.w11 = wy * wx;
    int iy1 = iy0 + 1, ix1 = ix0 + 1;
    bool vy0 = (iy0 >= 0) & (iy0 < Hn), vy1 = (iy1 >= 0) & (iy1 < Hn);
    bool vx0 = (ix0 >= 0) & (ix0 < Wn), vx1 = (ix1 >= 0) & (ix1 < Wn);
    m.v00 = vy0 & vx0; m.v01 = vy0 & vx1; m.v10 = vy1 & vx0; m.v11 = vy1 & vx1;
    m.o00 = iy0 * Wn + ix0; m.o01 = iy0 * Wn + ix1;
    m.o10 = iy1 * Wn + ix0; m.o11 = iy1 * Wn + ix1;
    return m;
}
// single fp16 store at row c
__device__ __forceinline__ void bstore(unsigned short* dst, int c, int p, float s) {
    dst[c * BROWS + p] = __half_as_ushort(__float2half_rn(s));
}

// ---------------------------------------------------------------------------
// Kernel 1: offset conv partials (+ fused A-fragment prep) — R12 form
// ---------------------------------------------------------------------------
__global__ __launch_bounds__(256) void off_kernel(const float* __restrict__ x,
                                                  const float* __restrict__ w_off,
                                                  const float* __restrict__ b_off,
                                                  const float* __restrict__ w_def) {
    {
        int gt = blockIdx.x * 256 + threadIdx.x;
        for (int it = gt; it < KK9 * 8 * 8 * 32; it += 512 * 256) {
            int lane = it & 31;
            int mt   = (it >> 5) & 7;
            int ks8  = (it >> 8) & 7;
            int kk   = it >> 11;
            int g  = lane >> 2, tg = lane & 3;
            int cb = ks8 * 16 + 2 * tg;
            int m  = mt * 16 + g;
            uint4 v;
            v.x = apack1(w_def, kk, m,     cb);
            v.y = apack1(w_def, kk, m + 8, cb);
            v.z = apack1(w_def, kk, m,     cb + 8);
            v.w = apack1(w_def, kk, m + 8, cb + 8);
            g_wAfrag[it] = v;
        }
    }

    __shared__ u64t wch2[32 * KK9 * 10];

    int chunk = blockIdx.x >> 7;
    int pixblk = blockIdx.x & 127;
    int cc = chunk * 32;

    int pix = pixblk * 256 + threadIdx.x;
    int w = pix & 63;
    int h = (pix >> 6) & 63;
    int b = pix >> 12;

    for (int i = threadIdx.x; i < 32 * KK9 * 9; i += 256) {
        int q  = i % 9;
        int jp = (i / 9) % KK9;
        int cl = i / (9 * KK9);
        float lo = w_off[((2 * jp)     * Cn + cc + cl) * 9 + q];
        float hi = w_off[((2 * jp + 1) * Cn + cc + cl) * 9 + q];
        wch2[(cl * KK9 + jp) * 10 + q] = pack2(lo, hi);
    }
    __syncthreads();

    u64t acc2[KK9];
#pragma unroll
    for (int jp = 0; jp < KK9; jp++)
        acc2[jp] = (chunk == 0) ? pack2(b_off[2 * jp], b_off[2 * jp + 1]) : 0ULL;

    for (int cl = 0; cl < 32; cl++) {
        const float* xb = x + ((b * Cn + cc + cl) * Hn) * Wn;
        u64t x2[9];
#pragma unroll
        for (int ky = 0; ky < 3; ky++)
#pragma unroll
            for (int kx = 0; kx < 3; kx++) {
                int y = h - 1 + ky, xx = w - 1 + kx;
                bool v = (y >= 0) & (y < Hn) & (xx >= 0) & (xx < Wn);
                float xv = v ? xb[y * Wn + xx] : 0.0f;
                x2[ky * 3 + kx] = pack2(xv, xv);
            }
#pragma unroll
        for (int jp = 0; jp < KK9; jp++) {
            const u64t* wp = &wch2[(cl * KK9 + jp) * 10];
            ulonglong2 w01 = *(const ulonglong2*)(wp);
            ulonglong2 w23 = *(const ulonglong2*)(wp + 2);
            ulonglong2 w45 = *(const ulonglong2*)(wp + 4);
            ulonglong2 w67 = *(const ulonglong2*)(wp + 6);
            u64t       w8  = wp[8];
            u64t a = acc2[jp];
            a = ffma2(w01.x, x2[0], a);
            a = ffma2(w01.y, x2[1], a);
            a = ffma2(w23.x, x2[2], a);
            a = ffma2(w23.y, x2[3], a);
            a = ffma2(w45.x, x2[4], a);
            a = ffma2(w45.y, x2[5], a);
            a = ffma2(w67.x, x2[6], a);
            a = ffma2(w67.y, x2[7], a);
            a = ffma2(w8,    x2[8], a);
            acc2[jp] = a;
        }
    }

    float* op = g_off_part + (size_t)chunk * Bn * NJ * Hn * Wn;
#pragma unroll
    for (int jp = 0; jp < KK9; jp++) {
        float lo, hi;
        unpack2(acc2[jp], lo, hi);
        op[((b * NJ + 2 * jp)     * Hn + h) * Wn + w] = lo;
        op[((b * NJ + 2 * jp + 1) * Hn + h) * Wn + w] = hi;
    }
}

// ---------------------------------------------------------------------------
// Kernel 2: distance-2 pipelined gather + single-term fp16 mma.sync GEMM.
// Gather loads for chunk j+1 issue before chunk j's MMAs; chunk j's values
// (loaded a full iteration earlier) are consumed after them.
// ---------------------------------------------------------------------------
__global__ __launch_bounds__(256, 2) void main_kernel(const float* __restrict__ x,
                                                      const float* __restrict__ b_def,
                                                      float* __restrict__ out) {
    extern __shared__ char sm[];
    unsigned short* sB = (unsigned short*)sm;
    uint32_t smB = smem_u32(sm);

    int tid  = threadIdx.x;
    int wid  = tid >> 5;
    int lane = tid & 31;
    int b = blockIdx.x >> 6;
    int h = blockIdx.x & 63;

    // warp tiling: 4m x 2n
    int wm = wid >> 1;
    int wn = wid & 1;
    int g  = lane >> 2, tg = lane & 3;

    float acc[2][4][4];
#pragma unroll
    for (int f = 0; f < 2; f++)
#pragma unroll
        for (int nf = 0; nf < 4; nf++)
#pragma unroll
            for (int q = 0; q < 4; q++) acc[f][nf][q] = 0.0f;

    // gather mapping: thread = (pixel p, 32-channel group)
    int p    = tid & 63;
    int cgrp = tid >> 6;
    const float* xb0 = x + (size_t)(b * Cn + cgrp * 32) * HW;

    // ldmatrix per-lane byte offset within a buffer
    int lr    = lane & 7;
    int khalf = ((lane >> 3) & 1) * 8;
    int pgrp  = lane >> 4;
    uint32_t browbase = (uint32_t)((khalf + lr) * BROWB + (wn * 32 + pgrp * 8) * 2);

    // ---- prologue: gather kk=0 into buffer 0 ----
    {
        Meta m0 = make_meta(b, h, p, 0);
#pragma unroll 8
        for (int ci = 0; ci < 32; ci++) {
            const float* xc = xb0 + ci * HW;
            float a00 = m0.v00 ? xc[m0.o00] : 0.0f;
            float a01 = m0.v01 ? xc[m0.o01] : 0.0f;
            float a10 = m0.v10 ? xc[m0.o10] : 0.0f;
            float a11 = m0.v11 ? xc[m0.o11] : 0.0f;
            float s = a00 * m0.w00 + a01 * m0.w01 + a10 * m0.w10 + a11 * m0.w11;
            bstore(sB, cgrp * 32 + ci, p, s);
        }
    }
    __syncthreads();

    // ---- main pipelined loop over kk ----
    for (int kk = 0; kk < KK9; kk++) {
        uint32_t curOff = (uint32_t)((kk & 1) * SMB_BYTES);
        unsigned short* nxtB = sB + ((kk + 1) & 1) * SMB_HALF_SHORTS;
        bool doG = (kk < KK9 - 1);
        Meta mn;
        if (doG) mn = make_meta(b, h, p, kk + 1);
        const uint4* ap = g_wAfrag + (size_t)kk * (8 * 8 * 32);

        // double-buffered gather registers (distance-2 pipeline)
        float gv[2][4][4];
        if (doG) {
#pragma unroll
            for (int q = 0; q < 4; q++) {
                const float* xc = xb0 + q * HW;
                gv[0][q][0] = mn.v00 ? xc[mn.o00] : 0.0f;
                gv[0][q][1] = mn.v01 ? xc[mn.o01] : 0.0f;
                gv[0][q][2] = mn.v10 ? xc[mn.o10] : 0.0f;
                gv[0][q][3] = mn.v11 ? xc[mn.o11] : 0.0f;
            }
        }

#pragma unroll
        for (int ks8 = 0; ks8 < 8; ks8++) {
            int cur = ks8 & 1;
            // issue next chunk's gather loads (consumed next iteration)
            if (doG && ks8 < 7) {
#pragma unroll
                for (int q = 0; q < 4; q++) {
                    const float* xc = xb0 + ((ks8 + 1) * 4 + q) * HW;
                    gv[cur ^ 1][q][0] = mn.v00 ? xc[mn.o00] : 0.0f;
                    gv[cur ^ 1][q][1] = mn.v01 ? xc[mn.o01] : 0.0f;
                    gv[cur ^ 1][q][2] = mn.v10 ? xc[mn.o10] : 0.0f;
                    gv[cur ^ 1][q][3] = mn.v11 ? xc[mn.o11] : 0.0f;
                }
            }

            // A fragments (2 m-frags)
            const uint4* a_hi = ap + ((size_t)ks8 * 8 + wm * 2) * 32 + lane;
            uint4 Ah0 = a_hi[0], Ah1 = a_hi[32];

            // B fragments: single s plane
            uint32_t addr = smB + curOff + browbase + (uint32_t)(ks8 * 16 * BROWB);
            uint32_t b0, b1, b2, b3, b4, b5, b6, b7;
            LDSM_X4_TRANS(b0, b1, b2, b3, addr);
            LDSM_X4_TRANS(b4, b5, b6, b7, addr + 32);

            MMA_F16(acc[0][0], Ah0, b0, b1);
            MMA_F16(acc[0][1], Ah0, b2, b3);
            MMA_F16(acc[0][2], Ah0, b4, b5);
            MMA_F16(acc[0][3], Ah0, b6, b7);
            MMA_F16(acc[1][0], Ah1, b0, b1);
            MMA_F16(acc[1][1], Ah1, b2, b3);
            MMA_F16(acc[1][2], Ah1, b4, b5);
            MMA_F16(acc[1][3], Ah1, b6, b7);

            // consume this chunk's gathered values (loaded last iteration)
            if (doG) {
#pragma unroll
                for (int q = 0; q < 4; q++) {
                    float s = gv[cur][q][0] * mn.w00 + gv[cur][q][1] * mn.w01
                            + gv[cur][q][2] * mn.w10 + gv[cur][q][3] * mn.w11;
                    bstore(nxtB, cgrp * 32 + ks8 * 4 + q, p, s);
                }
            }
        }
        __syncthreads();
    }

    // ---- Epilogue: D fragment -> gmem with bias ----
#pragma unroll
    for (int f = 0; f < 2; f++) {
        int oo = wm * 32 + f * 16 + g;
        float bd0 = b_def[oo];
        float bd1 = b_def[oo + 8];
        float* orow0 = out + (((size_t)b * On + oo) * Hn + h) * Wn;
        float* orow1 = orow0 + (size_t)8 * HW;
#pragma unroll
        for (int nf = 0; nf < 4; nf++) {
            int pp = wn * 32 + nf * 8 + 2 * tg;
            float2 v0 = { acc[f][nf][0] + bd0, acc[f][nf][1] + bd0 };
            float2 v1 = { acc[f][nf][2] + bd1, acc[f][nf][3] + bd1 };
            *(float2*)(orow0 + pp) = v0;
            *(float2*)(orow1 + pp) = v1;
        }
    }
}

// ---------------------------------------------------------------------------
extern "C" void kernel_launch(void* const* d_in, const int* in_sizes, int n_in,
                              void* d_out, int out_size) {
    const float* x     = (const float*)d_in[0];
    const float* w_off = (const float*)d_in[1];
    const float* b_off = (const float*)d_in[2];
    const float* w_def = (const float*)d_in[3];
    const float* b_def = (const float*)d_in[4];
    float* out = (float*)d_out;

    cudaFuncSetAttribute(main_kernel, cudaFuncAttributeMaxDynamicSharedMemorySize, SM_TOT);

    off_kernel<<<512, 256>>>(x, w_off, b_off, w_def);
    main_kernel<<<Bn * Hn, 256, SM_TOT>>>(x, b_def, out);
}